// round 3
// baseline (speedup 1.0000x reference)
#include <cuda_runtime.h>

// DilateAttention: B=8, C=384 (12 heads x 32), H=W=56, kernel 3x3, dilation 2, pad 2.
// q,k,v: [B, C, H, W] f32. out: [B, H, W, C] f32.
//
// R3: 2 pixels/thread. Per (channel, row) one thread loads three float2 windows
// [x0-2,x0-1][x0,x0+1][x0+2,x0+3]; pixel 0 uses .x lanes, pixel 1 uses .y lanes,
// serving all 3 x-neighbors of both pixels from 3 loads. All addressing is
// pointer-increment (no div/mod in hot loops). Output staged in smem once and
// written with fully-coalesced 128B-per-pixel float4 stores. One barrier total.

#define HD     32
#define HEADS  12
#define WD     56
#define HT     56
#define BD     8
#define HW     (WD * HT)
#define CTOT   384
#define XG     28           // x-groups per row (2 px each)
#define NTHR   128
#define PXB    (NTHR * 2)   // 256 pixels per block
#define PITCH  33           // smem stage pitch (floats)

__global__ __launch_bounds__(NTHR, 6)
void dilate_attn_kernel(const float* __restrict__ q,
                        const float* __restrict__ k,
                        const float* __restrict__ v,
                        float* __restrict__ out)
{
    __shared__ float stage[PXB * PITCH];   // 33.8 KB
    __shared__ int   sOb[PXB];             // 1 KB

    const int tid = threadIdx.x;
    const int gid = blockIdx.x * NTHR + tid;
    const int xg  = gid % XG;
    int r1        = gid / XG;
    const int y   = r1 % HT;
    int r2        = r1 / HT;
    const int head = r2 % HEADS;
    const int b    = r2 / HEADS;
    const int x0   = xg * 2;

    const int base = (b * CTOT + head * HD) * HW;
    {
        int ob = ((b * HT + y) * WD + x0) * CTOT + head * HD;
        sOb[2 * tid]     = ob;
        sOb[2 * tid + 1] = ob + CTOT;
    }

    const bool pOK = (xg > 0);        // left window in-bounds
    const bool rOK = (xg < XG - 1);   // right window in-bounds
    const bool yT  = (y >= 2);        // row y-2 valid
    const bool yB  = (y <= HT - 3);   // row y+2 valid
    const float2 zf2 = make_float2(0.0f, 0.0f);

    float a0[9], a1[9];
#pragma unroll
    for (int p = 0; p < 9; p++) { a0[p] = 0.0f; a1[p] = 0.0f; }

    // ================= K phase: logits =================
    {
        const float* qp  = q + base + y * WD + x0;
        const float* kr0 = k + base + (y - 2) * WD + x0;  // row y-2 (guarded)
        const float* kr1 = kr0 + 2 * WD;                  // row y
        const float* kr2 = kr1 + 2 * WD;                  // row y+2 (guarded)

#pragma unroll 8
        for (int c = 0; c < HD; c++) {
            const float2 qv = *(const float2*)qp;

            float2 P, Q, R;
            // row y-2
            P = (yT && pOK) ? *(const float2*)(kr0 - 2) : zf2;
            Q = yT          ? *(const float2*)(kr0)     : zf2;
            R = (yT && rOK) ? *(const float2*)(kr0 + 2) : zf2;
            a0[0] = fmaf(qv.x, P.x, a0[0]); a1[0] = fmaf(qv.y, P.y, a1[0]);
            a0[1] = fmaf(qv.x, Q.x, a0[1]); a1[1] = fmaf(qv.y, Q.y, a1[1]);
            a0[2] = fmaf(qv.x, R.x, a0[2]); a1[2] = fmaf(qv.y, R.y, a1[2]);
            // row y
            P = pOK ? *(const float2*)(kr1 - 2) : zf2;
            Q =       *(const float2*)(kr1);
            R = rOK ? *(const float2*)(kr1 + 2) : zf2;
            a0[3] = fmaf(qv.x, P.x, a0[3]); a1[3] = fmaf(qv.y, P.y, a1[3]);
            a0[4] = fmaf(qv.x, Q.x, a0[4]); a1[4] = fmaf(qv.y, Q.y, a1[4]);
            a0[5] = fmaf(qv.x, R.x, a0[5]); a1[5] = fmaf(qv.y, R.y, a1[5]);
            // row y+2
            P = (yB && pOK) ? *(const float2*)(kr2 - 2) : zf2;
            Q = yB          ? *(const float2*)(kr2)     : zf2;
            R = (yB && rOK) ? *(const float2*)(kr2 + 2) : zf2;
            a0[6] = fmaf(qv.x, P.x, a0[6]); a1[6] = fmaf(qv.y, P.y, a1[6]);
            a0[7] = fmaf(qv.x, Q.x, a0[7]); a1[7] = fmaf(qv.y, Q.y, a1[7]);
            a0[8] = fmaf(qv.x, R.x, a0[8]); a1[8] = fmaf(qv.y, R.y, a1[8]);

            qp += HW; kr0 += HW; kr1 += HW; kr2 += HW;
        }
    }

    // ================= softmax (normalization folded into weights) =================
    {
        const float scale = 0.17677669529663687f;  // 32^-0.5
        float m0 = -1e30f, m1 = -1e30f;
#pragma unroll
        for (int p = 0; p < 9; p++) {
            a0[p] *= scale; a1[p] *= scale;
            m0 = fmaxf(m0, a0[p]); m1 = fmaxf(m1, a1[p]);
        }
        float d0 = 0.0f, d1 = 0.0f;
#pragma unroll
        for (int p = 0; p < 9; p++) {
            a0[p] = __expf(a0[p] - m0); d0 += a0[p];
            a1[p] = __expf(a1[p] - m1); d1 += a1[p];
        }
        float i0 = 1.0f / d0, i1 = 1.0f / d1;
#pragma unroll
        for (int p = 0; p < 9; p++) { a0[p] *= i0; a1[p] *= i1; }
    }

    // ================= V phase: weighted sum, channel chunks of 8 =================
    {
        const float* vr0b = v + base + (y - 2) * WD + x0;

        for (int ch = 0; ch < 4; ch++) {
            float acc0[8], acc1[8];
            const float* p0 = vr0b + (ch * 8) * HW;

#pragma unroll
            for (int cc = 0; cc < 8; cc++) {
                const float* vr0 = p0 + cc * HW;
                const float* vr1 = vr0 + 2 * WD;
                const float* vr2 = vr1 + 2 * WD;

                float2 P, Q, R;
                float s0, s1;
                // row y-2
                P = (yT && pOK) ? *(const float2*)(vr0 - 2) : zf2;
                Q = yT          ? *(const float2*)(vr0)     : zf2;
                R = (yT && rOK) ? *(const float2*)(vr0 + 2) : zf2;
                s0 = a0[0] * P.x;             s1 = a1[0] * P.y;
                s0 = fmaf(a0[1], Q.x, s0);    s1 = fmaf(a1[1], Q.y, s1);
                s0 = fmaf(a0[2], R.x, s0);    s1 = fmaf(a1[2], R.y, s1);
                // row y
                P = pOK ? *(const float2*)(vr1 - 2) : zf2;
                Q =       *(const float2*)(vr1);
                R = rOK ? *(const float2*)(vr1 + 2) : zf2;
                s0 = fmaf(a0[3], P.x, s0);    s1 = fmaf(a1[3], P.y, s1);
                s0 = fmaf(a0[4], Q.x, s0);    s1 = fmaf(a1[4], Q.y, s1);
                s0 = fmaf(a0[5], R.x, s0);    s1 = fmaf(a1[5], R.y, s1);
                // row y+2
                P = (yB && pOK) ? *(const float2*)(vr2 - 2) : zf2;
                Q = yB          ? *(const float2*)(vr2)     : zf2;
                R = (yB && rOK) ? *(const float2*)(vr2 + 2) : zf2;
                s0 = fmaf(a0[6], P.x, s0);    s1 = fmaf(a1[6], P.y, s1);
                s0 = fmaf(a0[7], Q.x, s0);    s1 = fmaf(a1[7], Q.y, s1);
                s0 = fmaf(a0[8], R.x, s0);    s1 = fmaf(a1[8], R.y, s1);

                acc0[cc] = s0;
                acc1[cc] = s1;
            }

            // stage (different columns per chunk -> no cross-chunk hazard; single barrier later)
            const int c0 = ch * 8;
            float* st0 = &stage[(2 * tid)     * PITCH + c0];
            float* st1 = &stage[(2 * tid + 1) * PITCH + c0];
#pragma unroll
            for (int cc = 0; cc < 8; cc++) { st0[cc] = acc0[cc]; st1[cc] = acc1[cc]; }
        }
    }

    __syncthreads();

    // ================= coalesced store: 8 lanes per pixel, 128B per pixel =================
#pragma unroll
    for (int j = 0; j < 16; j++) {
        int idx = tid + NTHR * j;        // 0 .. 2047
        int px  = idx >> 3;              // 0 .. 255
        int ci  = (idx & 7) << 2;        // 0,4,...,28
        const float* sp = &stage[px * PITCH + ci];
        float4 val = make_float4(sp[0], sp[1], sp[2], sp[3]);
        *(float4*)(out + sOb[px] + ci) = val;
    }
}

extern "C" void kernel_launch(void* const* d_in, const int* in_sizes, int n_in,
                              void* d_out, int out_size)
{
    const float* q = (const float*)d_in[0];
    const float* k = (const float*)d_in[1];
    const float* v = (const float*)d_in[2];
    float* out = (float*)d_out;

    int total  = BD * HEADS * HT * XG;          // 150528 threads (2 px each)
    int blocks = total / NTHR;                  // 1176
    dilate_attn_kernel<<<blocks, NTHR>>>(q, k, v, out);
}

// round 4
// speedup vs baseline: 1.5590x; 1.5590x over previous
#include <cuda_runtime.h>

// DilateAttention: B=8, C=384 (12 heads x 32), H=W=56, kernel 3x3, dilation 2, pad 2.
// q,k,v: [B, C, H, W] f32. out: [B, H, W, C] f32.
//
// R4: 2 pixels/thread (x0, x0+1). For each (channel, row) three aligned float2
// loads at x0-2 / x0 / x0+2 serve both pixels' 3 x-neighbors (.x lanes -> px0,
// .y lanes -> px1). Boundary handling is BRANCHLESS: invalid (neighbor) base
// pointers are redirected to a zero-initialized __device__ buffer, reproducing
// unfold's zero padding exactly (OOB logit == 0, exp(0) counted in softmax).
// Channels processed in chunks of 8 in both phases to keep registers ~48.

#define HD     32
#define HEADS  12
#define WD     56
#define HT     56
#define BD     8
#define HW     (WD * HT)
#define CTOT   384
#define XG     28           // x-pairs per row
#define NTHR   256

// zero scratch: inner loop reads pp + c*HW for c in [0,8) -> needs 7*HW+2 floats.
__device__ float g_zero[7 * HW + 2];   // zero-initialized by CUDA

__global__ __launch_bounds__(NTHR)
void dilate_attn_kernel(const float* __restrict__ q,
                        const float* __restrict__ k,
                        const float* __restrict__ v,
                        float* __restrict__ out)
{
    const int gid  = blockIdx.x * NTHR + threadIdx.x;
    const int xg   = gid % XG;
    int r1         = gid / XG;
    const int y    = r1 % HT;
    int r2         = r1 / HT;
    const int head = r2 % HEADS;
    const int b    = r2 / HEADS;
    const int x0   = xg * 2;

    const int base = (b * CTOT + head * HD) * HW;
    const int pix  = y * WD + x0;

    // validity per window (both pixels OOB together for each window)
    const bool cL = (x0 >= 2);
    const bool cR = (x0 <= WD - 4);
    const bool yT = (y >= 2);
    const bool yB = (y <= HT - 3);

    const bool vmask[9] = {
        yT && cL, yT, yT && cR,
        cL,       true, cR,
        yB && cL, yB, yB && cR
    };
    const int voff[9] = {
        -2 * WD - 2, -2 * WD, -2 * WD + 2,
        -2,           0,       2,
         2 * WD - 2,  2 * WD,  2 * WD + 2
    };

    const float* zp = g_zero;
    const float* qc = q + base + pix;
    const float* kc = k + base + pix;
    const float* vc = v + base + pix;

    float a0[9], a1[9];
#pragma unroll
    for (int p = 0; p < 9; p++) { a0[p] = 0.0f; a1[p] = 0.0f; }

    // ================= K phase: logits (channel chunks of 8) =================
#pragma unroll
    for (int ch = 0; ch < 4; ch++) {
        float2 qv[8];
#pragma unroll
        for (int c = 0; c < 8; c++)
            qv[c] = *(const float2*)(qc + (ch * 8 + c) * HW);

#pragma unroll
        for (int p = 0; p < 9; p++) {
            const float* pp = vmask[p] ? (kc + ch * 8 * HW + voff[p]) : zp;
            float s0 = a0[p], s1 = a1[p];
#pragma unroll
            for (int c = 0; c < 8; c++) {
                float2 kv = *(const float2*)(pp + c * HW);
                s0 = fmaf(qv[c].x, kv.x, s0);
                s1 = fmaf(qv[c].y, kv.y, s1);
            }
            a0[p] = s0; a1[p] = s1;
        }
    }

    // ================= softmax (normalization folded into weights) =================
    {
        const float scale = 0.17677669529663687f;  // 32^-0.5
        float m0 = -1e30f, m1 = -1e30f;
#pragma unroll
        for (int p = 0; p < 9; p++) {
            a0[p] *= scale; a1[p] *= scale;
            m0 = fmaxf(m0, a0[p]); m1 = fmaxf(m1, a1[p]);
        }
        float d0 = 0.0f, d1 = 0.0f;
#pragma unroll
        for (int p = 0; p < 9; p++) {
            a0[p] = __expf(a0[p] - m0); d0 += a0[p];
            a1[p] = __expf(a1[p] - m1); d1 += a1[p];
        }
        float i0 = 1.0f / d0, i1 = 1.0f / d1;
#pragma unroll
        for (int p = 0; p < 9; p++) { a0[p] *= i0; a1[p] *= i1; }
    }

    // ================= V phase: weighted sum + direct stores =================
    const int ob = ((b * HT + y) * WD + x0) * CTOT + head * HD;

#pragma unroll
    for (int ch = 0; ch < 4; ch++) {
        float acc0[8], acc1[8];
#pragma unroll
        for (int c = 0; c < 8; c++) { acc0[c] = 0.0f; acc1[c] = 0.0f; }

#pragma unroll
        for (int p = 0; p < 9; p++) {
            const float* pp = vmask[p] ? (vc + ch * 8 * HW + voff[p]) : zp;
            const float w0 = a0[p], w1 = a1[p];
#pragma unroll
            for (int c = 0; c < 8; c++) {
                float2 vv = *(const float2*)(pp + c * HW);
                acc0[c] = fmaf(w0, vv.x, acc0[c]);
                acc1[c] = fmaf(w1, vv.y, acc1[c]);
            }
        }

        float* o0 = out + ob + ch * 8;
        *(float4*)(o0)            = make_float4(acc0[0], acc0[1], acc0[2], acc0[3]);
        *(float4*)(o0 + 4)        = make_float4(acc0[4], acc0[5], acc0[6], acc0[7]);
        *(float4*)(o0 + CTOT)     = make_float4(acc1[0], acc1[1], acc1[2], acc1[3]);
        *(float4*)(o0 + CTOT + 4) = make_float4(acc1[4], acc1[5], acc1[6], acc1[7]);
    }
}

extern "C" void kernel_launch(void* const* d_in, const int* in_sizes, int n_in,
                              void* d_out, int out_size)
{
    const float* q = (const float*)d_in[0];
    const float* k = (const float*)d_in[1];
    const float* v = (const float*)d_in[2];
    float* out = (float*)d_out;

    int total  = BD * HEADS * HT * XG;   // 150528 threads (2 px each)
    int blocks = total / NTHR;           // 588
    dilate_attn_kernel<<<blocks, NTHR>>>(q, k, v, out);
}

// round 5
// speedup vs baseline: 1.8594x; 1.1927x over previous
#include <cuda_runtime.h>

// DilateAttention: B=8, C=384 (12 heads x 32), H=W=56, kernel 3x3, dilation 2, pad 2.
// q,k,v: [B, C, H, W] f32. out: [B, H, W, C] f32.
//
// R5 = R1 structure (1 px/thread, guarded per-neighbor dot products) with:
//  - channel chunks of 16 (qv/acc register halving) + __launch_bounds__(256,5)
//    -> target <=51 regs, 62.5% occupancy (R1 was 64 regs / 39.5%)
//  - smem-staged output: scattered 8x STG.128/px -> 1 coalesced 128B store/px
// OOB neighbors skipped => logit stays 0, matching unfold's zero padding.

#define HD     32
#define HEADS  12
#define WD     56
#define HT     56
#define BD     8
#define HW     (WD * HT)
#define CTOT   384
#define NTHR   256
#define PITCH  33   // stage pitch in floats

__global__ __launch_bounds__(NTHR, 5)
void dilate_attn_kernel(const float* __restrict__ q,
                        const float* __restrict__ k,
                        const float* __restrict__ v,
                        float* __restrict__ out)
{
    __shared__ float stage[NTHR * PITCH];  // 33.8 KB
    __shared__ int   sOb[NTHR];            // 1 KB

    const int tid  = threadIdx.x;
    const int gid  = blockIdx.x * NTHR + tid;
    const int x    = gid % WD;
    int r1         = gid / WD;
    const int y    = r1 % HT;
    int r2         = r1 / HT;
    const int head = r2 % HEADS;
    const int b    = r2 / HEADS;

    const int base = (b * CTOT + head * HD) * HW;
    const int pix  = y * WD + x;

    sOb[tid] = ((b * HT + y) * WD + x) * CTOT + head * HD;

    const bool cL = (x >= 2);
    const bool cR = (x <= WD - 3);
    const bool yT = (y >= 2);
    const bool yB = (y <= HT - 3);

    const bool vmask[9] = {
        yT && cL, yT, yT && cR,
        cL,       true, cR,
        yB && cL, yB, yB && cR
    };
    const int voff[9] = {
        -2 * WD - 2, -2 * WD, -2 * WD + 2,
        -2,           0,       2,
         2 * WD - 2,  2 * WD,  2 * WD + 2
    };

    float attn[9];
#pragma unroll
    for (int p = 0; p < 9; p++) attn[p] = 0.0f;

    // ================= K phase: logits, channel chunks of 16 =================
    {
        const float* qc = q + base + pix;
        const float* kc = k + base + pix;
#pragma unroll
        for (int ch = 0; ch < 2; ch++) {
            float qv[16];
#pragma unroll
            for (int c = 0; c < 16; c++) qv[c] = qc[(ch * 16 + c) * HW];

#pragma unroll
            for (int p = 0; p < 9; p++) {
                if (vmask[p]) {
                    const float* kp = kc + ch * 16 * HW + voff[p];
                    float s = attn[p];
#pragma unroll
                    for (int c = 0; c < 16; c++) s = fmaf(qv[c], kp[c * HW], s);
                    attn[p] = s;
                }
            }
        }
    }

    // ================= softmax (normalization folded into weights) =================
    {
        const float scale = 0.17677669529663687f;  // 32^-0.5
        float m = -1e30f;
#pragma unroll
        for (int p = 0; p < 9; p++) { attn[p] *= scale; m = fmaxf(m, attn[p]); }
        float d = 0.0f;
#pragma unroll
        for (int p = 0; p < 9; p++) { attn[p] = __expf(attn[p] - m); d += attn[p]; }
        float inv = 1.0f / d;
#pragma unroll
        for (int p = 0; p < 9; p++) attn[p] *= inv;
    }

    // ================= V phase: weighted sum, staged to smem =================
    {
        const float* vc = v + base + pix;
#pragma unroll
        for (int ch = 0; ch < 2; ch++) {
            float acc[16];
#pragma unroll
            for (int c = 0; c < 16; c++) acc[c] = 0.0f;

#pragma unroll
            for (int p = 0; p < 9; p++) {
                if (vmask[p]) {
                    const float w = attn[p];
                    const float* vp = vc + ch * 16 * HW + voff[p];
#pragma unroll
                    for (int c = 0; c < 16; c++) acc[c] = fmaf(w, vp[c * HW], acc[c]);
                }
            }

            float* st = &stage[tid * PITCH + ch * 16];
#pragma unroll
            for (int c = 0; c < 16; c++) st[c] = acc[c];
        }
    }

    __syncthreads();

    // ================= coalesced store: 8 lanes per pixel, 128B per pixel =================
#pragma unroll
    for (int j = 0; j < 8; j++) {
        int idx = tid + NTHR * j;       // 0 .. 2047
        int px  = idx >> 3;             // 0 .. 255
        int ci  = (idx & 7) << 2;       // 0,4,...,28
        const float* sp = &stage[px * PITCH + ci];
        float4 val = make_float4(sp[0], sp[1], sp[2], sp[3]);
        *(float4*)(out + sOb[px] + ci) = val;
    }
}

extern "C" void kernel_launch(void* const* d_in, const int* in_sizes, int n_in,
                              void* d_out, int out_size)
{
    const float* q = (const float*)d_in[0];
    const float* k = (const float*)d_in[1];
    const float* v = (const float*)d_in[2];
    float* out = (float*)d_out;

    int total  = BD * HEADS * HT * WD;   // 301056 threads
    int blocks = total / NTHR;           // 1176
    dilate_attn_kernel<<<blocks, NTHR>>>(q, k, v, out);
}